// round 9
// baseline (speedup 1.0000x reference)
#include <cuda_runtime.h>
#include <cuda_fp16.h>
#include <math.h>
#include <stdint.h>

#define DIMC 1024
#define HEADS 16
#define HDIM 64
#define WIN 128
#define SEQ 8192
#define BATCH 4
#define MROWS (BATCH * SEQ)        // 32768
#define MLPH 2048
#define EPSLN 1e-5f

// ---------------- scratch (device globals; no runtime allocation) ----------
__device__ __half g_ln[(size_t)MROWS * DIMC];
__device__ __half g_qkv[(size_t)MROWS * 3 * DIMC];
__device__ __half g_attn[(size_t)MROWS * DIMC];
__device__ float  g_x2[(size_t)MROWS * DIMC];
__device__ __half g_g[(size_t)MROWS * MLPH];
__device__ __half g_wqkv[(size_t)3 * DIMC * DIMC];
__device__ __half g_wproj[(size_t)DIMC * DIMC];
__device__ __half g_wfc1[(size_t)MLPH * DIMC];
__device__ __half g_wfc2[(size_t)DIMC * MLPH];

// ---------------- helpers ---------------------------------------------------
__device__ __forceinline__ uint32_t s2u(const void* p) {
    uint32_t r;
    asm("{ .reg .u64 t; cvta.to.shared.u64 t, %1; cvt.u32.u64 %0, t; }" : "=r"(r) : "l"(p));
    return r;
}

// ---------------- fp32 -> fp16 converter -----------------------------------
__global__ void f2h_kernel(const float* __restrict__ src, __half* __restrict__ dst, int n4) {
    int i = blockIdx.x * blockDim.x + threadIdx.x;
    if (i < n4) {
        float4 v = reinterpret_cast<const float4*>(src)[i];
        reinterpret_cast<__half2*>(dst)[2 * i]     = __floats2half2_rn(v.x, v.y);
        reinterpret_cast<__half2*>(dst)[2 * i + 1] = __floats2half2_rn(v.z, v.w);
    }
}

// ---------------- LayerNorm (fp32 in, half out) ----------------------------
__global__ void ln_kernel(const float* __restrict__ x, const float* __restrict__ w,
                          const float* __restrict__ b, __half* __restrict__ out) {
    __shared__ float s_sum[8], s_sq[8];
    int row = blockIdx.x;
    const float4* xr = reinterpret_cast<const float4*>(x + (size_t)row * DIMC);
    float4 v = xr[threadIdx.x];
    float s = v.x + v.y + v.z + v.w;
    float q = v.x * v.x + v.y * v.y + v.z * v.z + v.w * v.w;
#pragma unroll
    for (int o = 16; o; o >>= 1) {
        s += __shfl_xor_sync(0xffffffffu, s, o);
        q += __shfl_xor_sync(0xffffffffu, q, o);
    }
    int warp = threadIdx.x >> 5, lane = threadIdx.x & 31;
    if (lane == 0) { s_sum[warp] = s; s_sq[warp] = q; }
    __syncthreads();
    float ts = 0.f, tq = 0.f;
#pragma unroll
    for (int i = 0; i < 8; i++) { ts += s_sum[i]; tq += s_sq[i]; }
    float mean = ts * (1.f / DIMC);
    float var = tq * (1.f / DIMC) - mean * mean;
    float rstd = rsqrtf(var + EPSLN);
    float4 wv = reinterpret_cast<const float4*>(w)[threadIdx.x];
    float4 bv = reinterpret_cast<const float4*>(b)[threadIdx.x];
    __half2 h0 = __floats2half2_rn((v.x - mean) * rstd * wv.x + bv.x,
                                   (v.y - mean) * rstd * wv.y + bv.y);
    __half2 h1 = __floats2half2_rn((v.z - mean) * rstd * wv.z + bv.z,
                                   (v.w - mean) * rstd * wv.w + bv.w);
    reinterpret_cast<__half2*>(out + (size_t)row * DIMC)[2 * threadIdx.x] = h0;
    reinterpret_cast<__half2*>(out + (size_t)row * DIMC)[2 * threadIdx.x + 1] = h1;
}

// ---------------- fp16 HMMA GEMM, 128x256 block, 64x64 warp tile -----------
// C[M,N] = A[M,K] @ W[N,K]^T + bias (+epilogue). acc fp32.
// 8 warps (2 M x 4 N), BK=32, 3-stage cp.async pipeline, ldmatrix fragments.
// EPI: 0 = bias (half out), 1 = bias + exact GELU (half out), 2 = bias + fp32 residual (float out)

#define BM 128
#define BN 256
#define BK 32
#define STAGES 3
#define ROWB 80                         // row stride bytes (32 halves + 8 pad)
#define A_STG_B (BM * ROWB)             // 10240
#define B_STG_B (BN * ROWB)             // 20480
#define GEMM_DYN (STAGES * (A_STG_B + B_STG_B) + 256)  // ~92.4 KB

template <int EPI, typename OT>
__global__ __launch_bounds__(256, 1)
void hmma_gemm(const __half* __restrict__ A, const __half* __restrict__ W,
               const float* __restrict__ bias, const float* __restrict__ res,
               OT* __restrict__ C, int M, int N, int K) {
    extern __shared__ char dsm[];
    const uint32_t sbase = (s2u(dsm) + 127u) & ~127u;
    const uint32_t aoff = sbase;
    const uint32_t boff = sbase + STAGES * A_STG_B;

    const int tid = threadIdx.x;
    const int lane = tid & 31, warp = tid >> 5;
    const int warp_m = warp >> 2, warp_n = warp & 3;
    const int grp = lane >> 2, tig = lane & 3;
    const int m0 = blockIdx.y * BM, n0 = blockIdx.x * BN;

    const __half* Ab = A + (size_t)m0 * K;
    const __half* Wb = W + (size_t)n0 * K;

    // ldmatrix lane address components (within a 16x16 ldmatrix.x4 footprint)
    const int aRowL = (lane & 7) + ((lane >> 3) & 1) * 8;
    const int aKL   = (lane >> 4) * 8;
    const int bRowL = (lane & 7) + ((lane >> 4) & 1) * 8;
    const int bKL   = ((lane >> 3) & 1) * 8;

    float acc[4][8][4];
#pragma unroll
    for (int mt = 0; mt < 4; mt++)
#pragma unroll
        for (int nt = 0; nt < 8; nt++)
#pragma unroll
            for (int i = 0; i < 4; i++) acc[mt][nt][i] = 0.f;

    // ---- stage loader: cp.async 16B chunks (A: 512 chunks, B: 1024 chunks) ----
    auto load_stage = [&](int chunk, int s) {
        const int kc = chunk * BK;
        const uint32_t abuf = aoff + s * A_STG_B;
        const uint32_t bbuf = boff + s * B_STG_B;
#pragma unroll
        for (int i = 0; i < 2; i++) {
            int flat = tid + i * 256;               // 0..511
            int row = flat >> 2, cg = flat & 3;
            const void* src = Ab + (size_t)row * K + kc + cg * 8;
            uint32_t dst = abuf + row * ROWB + cg * 16;
            asm volatile("cp.async.cg.shared.global [%0], [%1], 16;" :: "r"(dst), "l"(src));
        }
#pragma unroll
        for (int i = 0; i < 4; i++) {
            int flat = tid + i * 256;               // 0..1023
            int row = flat >> 2, cg = flat & 3;
            const void* src = Wb + (size_t)row * K + kc + cg * 8;
            uint32_t dst = bbuf + row * ROWB + cg * 16;
            asm volatile("cp.async.cg.shared.global [%0], [%1], 16;" :: "r"(dst), "l"(src));
        }
        asm volatile("cp.async.commit_group;");
    };

    const int KIT = K / BK;
    load_stage(0, 0);
    load_stage(1, 1);

    for (int it = 0; it < KIT; ++it) {
        asm volatile("cp.async.wait_group %0;" :: "n"(STAGES - 2));
        __syncthreads();

        const int s = it % STAGES;
        const uint32_t abufs = aoff + s * A_STG_B;
        const uint32_t bbufs = boff + s * B_STG_B;

#pragma unroll
        for (int kb = 0; kb < BK; kb += 16) {
            unsigned af[4][4], bf[4][4];
#pragma unroll
            for (int mt = 0; mt < 4; mt++) {
                uint32_t addr = abufs + (uint32_t)(warp_m * 64 + mt * 16 + aRowL) * ROWB +
                                (uint32_t)(kb + aKL) * 2;
                asm volatile("ldmatrix.sync.aligned.m8n8.x4.shared.b16 {%0,%1,%2,%3}, [%4];"
                             : "=r"(af[mt][0]), "=r"(af[mt][1]), "=r"(af[mt][2]), "=r"(af[mt][3])
                             : "r"(addr));
            }
#pragma unroll
            for (int ntp = 0; ntp < 4; ntp++) {
                uint32_t addr = bbufs + (uint32_t)(warp_n * 64 + ntp * 16 + bRowL) * ROWB +
                                (uint32_t)(kb + bKL) * 2;
                asm volatile("ldmatrix.sync.aligned.m8n8.x4.shared.b16 {%0,%1,%2,%3}, [%4];"
                             : "=r"(bf[ntp][0]), "=r"(bf[ntp][1]), "=r"(bf[ntp][2]), "=r"(bf[ntp][3])
                             : "r"(addr));
            }
#pragma unroll
            for (int mt = 0; mt < 4; mt++)
#pragma unroll
                for (int nt = 0; nt < 8; nt++) {
                    const unsigned* bb = &bf[nt >> 1][(nt & 1) * 2];
                    asm volatile(
                        "mma.sync.aligned.m16n8k16.row.col.f32.f16.f16.f32 "
                        "{%0,%1,%2,%3}, {%4,%5,%6,%7}, {%8,%9}, {%0,%1,%2,%3};"
                        : "+f"(acc[mt][nt][0]), "+f"(acc[mt][nt][1]),
                          "+f"(acc[mt][nt][2]), "+f"(acc[mt][nt][3])
                        : "r"(af[mt][0]), "r"(af[mt][1]), "r"(af[mt][2]), "r"(af[mt][3]),
                          "r"(bb[0]), "r"(bb[1]));
                }
        }
        __syncthreads();

        const int nxt = it + STAGES - 1;
        if (nxt < KIT) load_stage(nxt, nxt % STAGES);
    }

    // ---- epilogue ----
#pragma unroll
    for (int mt = 0; mt < 4; mt++) {
#pragma unroll
        for (int half_ = 0; half_ < 2; half_++) {
            int r = m0 + warp_m * 64 + mt * 16 + grp + half_ * 8;
#pragma unroll
            for (int nt = 0; nt < 8; nt++) {
                int c = n0 + warp_n * 64 + nt * 8 + tig * 2;
                float v0 = acc[mt][nt][half_ * 2 + 0] + __ldg(&bias[c]);
                float v1 = acc[mt][nt][half_ * 2 + 1] + __ldg(&bias[c + 1]);
                if (EPI == 1) {
                    v0 = 0.5f * v0 * (1.0f + erff(v0 * 0.70710678118654752f));
                    v1 = 0.5f * v1 * (1.0f + erff(v1 * 0.70710678118654752f));
                }
                if (EPI == 2) {
                    const float2 rr = *reinterpret_cast<const float2*>(res + (size_t)r * N + c);
                    v0 += rr.x; v1 += rr.y;
                }
                if (sizeof(OT) == 2) {
                    *reinterpret_cast<__half2*>((__half*)C + (size_t)r * N + c) =
                        __floats2half2_rn(v0, v1);
                } else {
                    *reinterpret_cast<float2*>((float*)C + (size_t)r * N + c) =
                        make_float2(v0, v1);
                }
            }
        }
    }
}

// ---------------- Windowed attention (half in, half out, fp32 math) --------
__global__ __launch_bounds__(128)
void attn_kernel(const __half* __restrict__ qkv, __half* __restrict__ out) {
    __shared__ float ks[64 * 64];
    __shared__ float vs[64 * 64];
    int w = blockIdx.x, h = blockIdx.y, b = blockIdx.z;
    int q = threadIdx.x;
    size_t rowbase = ((size_t)b * SEQ + (size_t)w * WIN);

    const __half2* qrow = reinterpret_cast<const __half2*>(
        qkv + (rowbase + q) * (3 * DIMC) + h * HDIM);
    float4 qv[16];
#pragma unroll
    for (int i = 0; i < 16; i++) {
        float2 a = __half22float2(qrow[2 * i]);
        float2 bb = __half22float2(qrow[2 * i + 1]);
        qv[i] = make_float4(a.x, a.y, bb.x, bb.y);
    }

    float m = -1e30f, l = 0.f;
    float4 acc[16];
#pragma unroll
    for (int i = 0; i < 16; i++) acc[i] = make_float4(0.f, 0.f, 0.f, 0.f);

    for (int c = 0; c < 2; c++) {
        __syncthreads();
        {
            int r = threadIdx.x >> 1;
            int part = threadIdx.x & 1;
            const __half2* krow = reinterpret_cast<const __half2*>(
                qkv + (rowbase + c * 64 + r) * (3 * DIMC) + DIMC + h * HDIM + part * 32);
            const __half2* vrow = reinterpret_cast<const __half2*>(
                qkv + (rowbase + c * 64 + r) * (3 * DIMC) + 2 * DIMC + h * HDIM + part * 32);
            float* kd = &ks[r * 64 + part * 32];
            float* vd = &vs[r * 64 + part * 32];
#pragma unroll
            for (int i = 0; i < 16; i++) {
                float2 kf = __half22float2(krow[i]);
                float2 vf = __half22float2(vrow[i]);
                kd[2 * i] = kf.x; kd[2 * i + 1] = kf.y;
                vd[2 * i] = vf.x; vd[2 * i + 1] = vf.y;
            }
        }
        __syncthreads();

        for (int j = 0; j < 64; j++) {
            const float4* kj = reinterpret_cast<const float4*>(&ks[j * 64]);
            float s = 0.f;
#pragma unroll
            for (int i = 0; i < 16; i++) {
                float4 kk = kj[i];
                s += qv[i].x * kk.x + qv[i].y * kk.y + qv[i].z * kk.z + qv[i].w * kk.w;
            }
            s *= 0.125f;
            float mn = fmaxf(m, s);
            float corr = __expf(m - mn);
            float p = __expf(s - mn);
            l = l * corr + p;
            const float4* vj = reinterpret_cast<const float4*>(&vs[j * 64]);
#pragma unroll
            for (int i = 0; i < 16; i++) {
                float4 vv = vj[i];
                acc[i].x = acc[i].x * corr + p * vv.x;
                acc[i].y = acc[i].y * corr + p * vv.y;
                acc[i].z = acc[i].z * corr + p * vv.z;
                acc[i].w = acc[i].w * corr + p * vv.w;
            }
            m = mn;
        }
    }

    float inv = 1.f / l;
    __half2* orow = reinterpret_cast<__half2*>(out + (rowbase + q) * DIMC + h * HDIM);
#pragma unroll
    for (int i = 0; i < 16; i++) {
        float4 o = acc[i];
        orow[2 * i]     = __floats2half2_rn(o.x * inv, o.y * inv);
        orow[2 * i + 1] = __floats2half2_rn(o.z * inv, o.w * inv);
    }
}

// ---------------- launch --------------------------------------------------
extern "C" void kernel_launch(void* const* d_in, const int* in_sizes, int n_in,
                              void* d_out, int out_size) {
    const float* x      = (const float*)d_in[0];
    const float* ln1_w  = (const float*)d_in[1];
    const float* ln1_b  = (const float*)d_in[2];
    const float* qkv_w  = (const float*)d_in[3];
    const float* qkv_b  = (const float*)d_in[4];
    const float* proj_w = (const float*)d_in[5];
    const float* proj_b = (const float*)d_in[6];
    const float* ln2_w  = (const float*)d_in[7];
    const float* ln2_b  = (const float*)d_in[8];
    const float* fc1_w  = (const float*)d_in[9];
    const float* fc1_b  = (const float*)d_in[10];
    const float* fc2_w  = (const float*)d_in[11];
    const float* fc2_b  = (const float*)d_in[12];
    float* out = (float*)d_out;

    __half *p_ln, *p_qkv, *p_attn, *p_g, *p_wqkv, *p_wproj, *p_wfc1, *p_wfc2;
    float* p_x2;
    cudaGetSymbolAddress((void**)&p_ln, g_ln);
    cudaGetSymbolAddress((void**)&p_qkv, g_qkv);
    cudaGetSymbolAddress((void**)&p_attn, g_attn);
    cudaGetSymbolAddress((void**)&p_x2, g_x2);
    cudaGetSymbolAddress((void**)&p_g, g_g);
    cudaGetSymbolAddress((void**)&p_wqkv, g_wqkv);
    cudaGetSymbolAddress((void**)&p_wproj, g_wproj);
    cudaGetSymbolAddress((void**)&p_wfc1, g_wfc1);
    cudaGetSymbolAddress((void**)&p_wfc2, g_wfc2);

    static bool attr_done = false;
    if (!attr_done) {
        cudaFuncSetAttribute(hmma_gemm<0, __half>, cudaFuncAttributeMaxDynamicSharedMemorySize, GEMM_DYN);
        cudaFuncSetAttribute(hmma_gemm<1, __half>, cudaFuncAttributeMaxDynamicSharedMemorySize, GEMM_DYN);
        cudaFuncSetAttribute(hmma_gemm<2, float>,  cudaFuncAttributeMaxDynamicSharedMemorySize, GEMM_DYN);
        attr_done = true;
    }

    // 0. weight conversion
    {
        int n;
        n = 3 * DIMC * DIMC / 4; f2h_kernel<<<(n + 255) / 256, 256>>>(qkv_w, p_wqkv, n);
        n = DIMC * DIMC / 4;     f2h_kernel<<<(n + 255) / 256, 256>>>(proj_w, p_wproj, n);
        n = MLPH * DIMC / 4;     f2h_kernel<<<(n + 255) / 256, 256>>>(fc1_w, p_wfc1, n);
        n = DIMC * MLPH / 4;     f2h_kernel<<<(n + 255) / 256, 256>>>(fc2_w, p_wfc2, n);
    }

    // 1. LN1
    ln_kernel<<<MROWS, 256>>>(x, ln1_w, ln1_b, p_ln);

    // 2. QKV
    {
        dim3 grid(3 * DIMC / BN, MROWS / BM);
        hmma_gemm<0, __half><<<grid, 256, GEMM_DYN>>>(p_ln, p_wqkv, qkv_b, nullptr, p_qkv,
                                                      MROWS, 3 * DIMC, DIMC);
    }

    // 3. Windowed attention
    {
        dim3 grid(SEQ / WIN, HEADS, BATCH);
        attn_kernel<<<grid, 128>>>(p_qkv, p_attn);
    }

    // 4. Proj + residual
    {
        dim3 grid(DIMC / BN, MROWS / BM);
        hmma_gemm<2, float><<<grid, 256, GEMM_DYN>>>(p_attn, p_wproj, proj_b, x, p_x2,
                                                     MROWS, DIMC, DIMC);
    }

    // 5. LN2
    ln_kernel<<<MROWS, 256>>>(p_x2, ln2_w, ln2_b, p_ln);

    // 6. FC1 + GELU
    {
        dim3 grid(MLPH / BN, MROWS / BM);
        hmma_gemm<1, __half><<<grid, 256, GEMM_DYN>>>(p_ln, p_wfc1, fc1_b, nullptr, p_g,
                                                      MROWS, MLPH, DIMC);
    }

    // 7. FC2 + residual
    {
        dim3 grid(DIMC / BN, MROWS / BM);
        hmma_gemm<2, float><<<grid, 256, GEMM_DYN>>>(p_g, p_wfc2, fc2_b, p_x2, out,
                                                     MROWS, DIMC, MLPH);
    }
}

// round 10
// speedup vs baseline: 1.1280x; 1.1280x over previous
#include <cuda_runtime.h>
#include <cuda_fp16.h>
#include <math.h>
#include <stdint.h>

#define DIMC 1024
#define HEADS 16
#define HDIM 64
#define WIN 128
#define SEQ 8192
#define BATCH 4
#define MROWS (BATCH * SEQ)        // 32768
#define MLPH 2048
#define EPSLN 1e-5f

// ---------------- scratch (device globals; no runtime allocation) ----------
__device__ __half g_ln[(size_t)MROWS * DIMC];
__device__ __half g_qkv[(size_t)MROWS * 3 * DIMC];
__device__ __half g_attn[(size_t)MROWS * DIMC];
__device__ float  g_x2[(size_t)MROWS * DIMC];
__device__ __half g_g[(size_t)MROWS * MLPH];
__device__ __half g_wqkv[(size_t)3 * DIMC * DIMC];
__device__ __half g_wproj[(size_t)DIMC * DIMC];
__device__ __half g_wfc1[(size_t)MLPH * DIMC];
__device__ __half g_wfc2[(size_t)DIMC * MLPH];

// ---------------- helpers ---------------------------------------------------
__device__ __forceinline__ uint32_t s2u(const void* p) {
    uint32_t r;
    asm("{ .reg .u64 t; cvta.to.shared.u64 t, %1; cvt.u32.u64 %0, t; }" : "=r"(r) : "l"(p));
    return r;
}

// ---------------- fp32 -> fp16 converter -----------------------------------
__global__ void f2h_kernel(const float* __restrict__ src, __half* __restrict__ dst, int n4) {
    int i = blockIdx.x * blockDim.x + threadIdx.x;
    if (i < n4) {
        float4 v = reinterpret_cast<const float4*>(src)[i];
        reinterpret_cast<__half2*>(dst)[2 * i]     = __floats2half2_rn(v.x, v.y);
        reinterpret_cast<__half2*>(dst)[2 * i + 1] = __floats2half2_rn(v.z, v.w);
    }
}

// ---------------- LayerNorm (fp32 in, half out) ----------------------------
__global__ void ln_kernel(const float* __restrict__ x, const float* __restrict__ w,
                          const float* __restrict__ b, __half* __restrict__ out) {
    __shared__ float s_sum[8], s_sq[8];
    int row = blockIdx.x;
    const float4* xr = reinterpret_cast<const float4*>(x + (size_t)row * DIMC);
    float4 v = xr[threadIdx.x];
    float s = v.x + v.y + v.z + v.w;
    float q = v.x * v.x + v.y * v.y + v.z * v.z + v.w * v.w;
#pragma unroll
    for (int o = 16; o; o >>= 1) {
        s += __shfl_xor_sync(0xffffffffu, s, o);
        q += __shfl_xor_sync(0xffffffffu, q, o);
    }
    int warp = threadIdx.x >> 5, lane = threadIdx.x & 31;
    if (lane == 0) { s_sum[warp] = s; s_sq[warp] = q; }
    __syncthreads();
    float ts = 0.f, tq = 0.f;
#pragma unroll
    for (int i = 0; i < 8; i++) { ts += s_sum[i]; tq += s_sq[i]; }
    float mean = ts * (1.f / DIMC);
    float var = tq * (1.f / DIMC) - mean * mean;
    float rstd = rsqrtf(var + EPSLN);
    float4 wv = reinterpret_cast<const float4*>(w)[threadIdx.x];
    float4 bv = reinterpret_cast<const float4*>(b)[threadIdx.x];
    __half2 h0 = __floats2half2_rn((v.x - mean) * rstd * wv.x + bv.x,
                                   (v.y - mean) * rstd * wv.y + bv.y);
    __half2 h1 = __floats2half2_rn((v.z - mean) * rstd * wv.z + bv.z,
                                   (v.w - mean) * rstd * wv.w + bv.w);
    reinterpret_cast<__half2*>(out + (size_t)row * DIMC)[2 * threadIdx.x] = h0;
    reinterpret_cast<__half2*>(out + (size_t)row * DIMC)[2 * threadIdx.x + 1] = h1;
}

// ---------------- fp16 HMMA GEMM, 128x128 block, 64x32 warp tile -----------
// C[M,N] = A[M,K] @ W[N,K]^T + bias (+epilogue). acc fp32.
// 8 warps (2 M x 4 N), BK=32, 4-stage cp.async pipeline, ldmatrix, 2 CTAs/SM.
// EPI: 0 = bias (half out), 1 = bias + exact GELU (half out), 2 = bias + fp32 residual (float out)

#define BM 128
#define BN 128
#define BK 32
#define STAGES 4
#define ROWB 80                         // row stride bytes (32 halves + 8 pad)
#define A_STG_B (BM * ROWB)             // 10240
#define B_STG_B (BN * ROWB)             // 10240
#define GEMM_DYN (STAGES * (A_STG_B + B_STG_B) + 256)  // ~82.2 KB

template <int EPI, typename OT>
__global__ __launch_bounds__(256, 2)
void hmma_gemm(const __half* __restrict__ A, const __half* __restrict__ W,
               const float* __restrict__ bias, const float* __restrict__ res,
               OT* __restrict__ C, int M, int N, int K) {
    extern __shared__ char dsm[];
    const uint32_t sbase = (s2u(dsm) + 127u) & ~127u;
    const uint32_t aoff = sbase;
    const uint32_t boff = sbase + STAGES * A_STG_B;

    const int tid = threadIdx.x;
    const int lane = tid & 31, warp = tid >> 5;
    const int warp_m = warp >> 2, warp_n = warp & 3;
    const int grp = lane >> 2, tig = lane & 3;
    const int m0 = blockIdx.y * BM, n0 = blockIdx.x * BN;

    const __half* Ab = A + (size_t)m0 * K;
    const __half* Wb = W + (size_t)n0 * K;

    // ldmatrix lane address components
    const int aRowL = (lane & 7) + ((lane >> 3) & 1) * 8;
    const int aKL   = (lane >> 4) * 8;
    const int bRowL = (lane & 7) + ((lane >> 4) & 1) * 8;
    const int bKL   = ((lane >> 3) & 1) * 8;

    float acc[4][4][4];
#pragma unroll
    for (int mt = 0; mt < 4; mt++)
#pragma unroll
        for (int nt = 0; nt < 4; nt++)
#pragma unroll
            for (int i = 0; i < 4; i++) acc[mt][nt][i] = 0.f;

    // ---- stage loader: cp.async 16B chunks (A: 512 chunks, B: 512 chunks) ----
    auto load_stage = [&](int chunk, int s) {
        const int kc = chunk * BK;
        const uint32_t abuf = aoff + s * A_STG_B;
        const uint32_t bbuf = boff + s * B_STG_B;
#pragma unroll
        for (int i = 0; i < 2; i++) {
            int flat = tid + i * 256;               // 0..511
            int row = flat >> 2, cg = flat & 3;
            const void* srca = Ab + (size_t)row * K + kc + cg * 8;
            uint32_t dsta = abuf + row * ROWB + cg * 16;
            asm volatile("cp.async.cg.shared.global [%0], [%1], 16;" :: "r"(dsta), "l"(srca));
            const void* srcb = Wb + (size_t)row * K + kc + cg * 8;
            uint32_t dstb = bbuf + row * ROWB + cg * 16;
            asm volatile("cp.async.cg.shared.global [%0], [%1], 16;" :: "r"(dstb), "l"(srcb));
        }
        asm volatile("cp.async.commit_group;");
    };

    const int KIT = K / BK;
#pragma unroll
    for (int p = 0; p < STAGES - 1; p++) load_stage(p, p);

    for (int it = 0; it < KIT; ++it) {
        asm volatile("cp.async.wait_group %0;" :: "n"(STAGES - 2));
        __syncthreads();

        const int nxt = it + STAGES - 1;
        if (nxt < KIT) load_stage(nxt, nxt % STAGES);

        const int s = it % STAGES;
        const uint32_t abufs = aoff + s * A_STG_B;
        const uint32_t bbufs = boff + s * B_STG_B;

#pragma unroll
        for (int kb = 0; kb < BK; kb += 16) {
            unsigned af[4][4], bf[2][4];
#pragma unroll
            for (int mt = 0; mt < 4; mt++) {
                uint32_t addr = abufs + (uint32_t)(warp_m * 64 + mt * 16 + aRowL) * ROWB +
                                (uint32_t)(kb + aKL) * 2;
                asm volatile("ldmatrix.sync.aligned.m8n8.x4.shared.b16 {%0,%1,%2,%3}, [%4];"
                             : "=r"(af[mt][0]), "=r"(af[mt][1]), "=r"(af[mt][2]), "=r"(af[mt][3])
                             : "r"(addr));
            }
#pragma unroll
            for (int ntp = 0; ntp < 2; ntp++) {
                uint32_t addr = bbufs + (uint32_t)(warp_n * 32 + ntp * 16 + bRowL) * ROWB +
                                (uint32_t)(kb + bKL) * 2;
                asm volatile("ldmatrix.sync.aligned.m8n8.x4.shared.b16 {%0,%1,%2,%3}, [%4];"
                             : "=r"(bf[ntp][0]), "=r"(bf[ntp][1]), "=r"(bf[ntp][2]), "=r"(bf[ntp][3])
                             : "r"(addr));
            }
#pragma unroll
            for (int mt = 0; mt < 4; mt++)
#pragma unroll
                for (int nt = 0; nt < 4; nt++) {
                    const unsigned* bb = &bf[nt >> 1][(nt & 1) * 2];
                    asm volatile(
                        "mma.sync.aligned.m16n8k16.row.col.f32.f16.f16.f32 "
                        "{%0,%1,%2,%3}, {%4,%5,%6,%7}, {%8,%9}, {%0,%1,%2,%3};"
                        : "+f"(acc[mt][nt][0]), "+f"(acc[mt][nt][1]),
                          "+f"(acc[mt][nt][2]), "+f"(acc[mt][nt][3])
                        : "r"(af[mt][0]), "r"(af[mt][1]), "r"(af[mt][2]), "r"(af[mt][3]),
                          "r"(bb[0]), "r"(bb[1]));
                }
        }
    }

    // ---- epilogue ----
#pragma unroll
    for (int mt = 0; mt < 4; mt++) {
#pragma unroll
        for (int half_ = 0; half_ < 2; half_++) {
            int r = m0 + warp_m * 64 + mt * 16 + grp + half_ * 8;
#pragma unroll
            for (int nt = 0; nt < 4; nt++) {
                int c = n0 + warp_n * 32 + nt * 8 + tig * 2;
                float v0 = acc[mt][nt][half_ * 2 + 0] + __ldg(&bias[c]);
                float v1 = acc[mt][nt][half_ * 2 + 1] + __ldg(&bias[c + 1]);
                if (EPI == 1) {
                    v0 = 0.5f * v0 * (1.0f + erff(v0 * 0.70710678118654752f));
                    v1 = 0.5f * v1 * (1.0f + erff(v1 * 0.70710678118654752f));
                }
                if (EPI == 2) {
                    const float2 rr = *reinterpret_cast<const float2*>(res + (size_t)r * N + c);
                    v0 += rr.x; v1 += rr.y;
                }
                if (sizeof(OT) == 2) {
                    *reinterpret_cast<__half2*>((__half*)C + (size_t)r * N + c) =
                        __floats2half2_rn(v0, v1);
                } else {
                    *reinterpret_cast<float2*>((float*)C + (size_t)r * N + c) =
                        make_float2(v0, v1);
                }
            }
        }
    }
}

// ---------------- Windowed attention (half in, half out, fp32 math) --------
__global__ __launch_bounds__(128)
void attn_kernel(const __half* __restrict__ qkv, __half* __restrict__ out) {
    __shared__ float ks[64 * 64];
    __shared__ float vs[64 * 64];
    int w = blockIdx.x, h = blockIdx.y, b = blockIdx.z;
    int q = threadIdx.x;
    size_t rowbase = ((size_t)b * SEQ + (size_t)w * WIN);

    const __half2* qrow = reinterpret_cast<const __half2*>(
        qkv + (rowbase + q) * (3 * DIMC) + h * HDIM);
    float4 qv[16];
#pragma unroll
    for (int i = 0; i < 16; i++) {
        float2 a = __half22float2(qrow[2 * i]);
        float2 bb = __half22float2(qrow[2 * i + 1]);
        qv[i] = make_float4(a.x, a.y, bb.x, bb.y);
    }

    float m = -1e30f, l = 0.f;
    float4 acc[16];
#pragma unroll
    for (int i = 0; i < 16; i++) acc[i] = make_float4(0.f, 0.f, 0.f, 0.f);

    for (int c = 0; c < 2; c++) {
        __syncthreads();
        {
            int r = threadIdx.x >> 1;
            int part = threadIdx.x & 1;
            const __half2* krow = reinterpret_cast<const __half2*>(
                qkv + (rowbase + c * 64 + r) * (3 * DIMC) + DIMC + h * HDIM + part * 32);
            const __half2* vrow = reinterpret_cast<const __half2*>(
                qkv + (rowbase + c * 64 + r) * (3 * DIMC) + 2 * DIMC + h * HDIM + part * 32);
            float* kd = &ks[r * 64 + part * 32];
            float* vd = &vs[r * 64 + part * 32];
#pragma unroll
            for (int i = 0; i < 16; i++) {
                float2 kf = __half22float2(krow[i]);
                float2 vf = __half22float2(vrow[i]);
                kd[2 * i] = kf.x; kd[2 * i + 1] = kf.y;
                vd[2 * i] = vf.x; vd[2 * i + 1] = vf.y;
            }
        }
        __syncthreads();

        for (int j = 0; j < 64; j++) {
            const float4* kj = reinterpret_cast<const float4*>(&ks[j * 64]);
            float s = 0.f;
#pragma unroll
            for (int i = 0; i < 16; i++) {
                float4 kk = kj[i];
                s += qv[i].x * kk.x + qv[i].y * kk.y + qv[i].z * kk.z + qv[i].w * kk.w;
            }
            s *= 0.125f;
            float mn = fmaxf(m, s);
            float corr = __expf(m - mn);
            float p = __expf(s - mn);
            l = l * corr + p;
            const float4* vj = reinterpret_cast<const float4*>(&vs[j * 64]);
#pragma unroll
            for (int i = 0; i < 16; i++) {
                float4 vv = vj[i];
                acc[i].x = acc[i].x * corr + p * vv.x;
                acc[i].y = acc[i].y * corr + p * vv.y;
                acc[i].z = acc[i].z * corr + p * vv.z;
                acc[i].w = acc[i].w * corr + p * vv.w;
            }
            m = mn;
        }
    }

    float inv = 1.f / l;
    __half2* orow = reinterpret_cast<__half2*>(out + (rowbase + q) * DIMC + h * HDIM);
#pragma unroll
    for (int i = 0; i < 16; i++) {
        float4 o = acc[i];
        orow[2 * i]     = __floats2half2_rn(o.x * inv, o.y * inv);
        orow[2 * i + 1] = __floats2half2_rn(o.z * inv, o.w * inv);
    }
}

// ---------------- launch --------------------------------------------------
extern "C" void kernel_launch(void* const* d_in, const int* in_sizes, int n_in,
                              void* d_out, int out_size) {
    const float* x      = (const float*)d_in[0];
    const float* ln1_w  = (const float*)d_in[1];
    const float* ln1_b  = (const float*)d_in[2];
    const float* qkv_w  = (const float*)d_in[3];
    const float* qkv_b  = (const float*)d_in[4];
    const float* proj_w = (const float*)d_in[5];
    const float* proj_b = (const float*)d_in[6];
    const float* ln2_w  = (const float*)d_in[7];
    const float* ln2_b  = (const float*)d_in[8];
    const float* fc1_w  = (const float*)d_in[9];
    const float* fc1_b  = (const float*)d_in[10];
    const float* fc2_w  = (const float*)d_in[11];
    const float* fc2_b  = (const float*)d_in[12];
    float* out = (float*)d_out;

    __half *p_ln, *p_qkv, *p_attn, *p_g, *p_wqkv, *p_wproj, *p_wfc1, *p_wfc2;
    float* p_x2;
    cudaGetSymbolAddress((void**)&p_ln, g_ln);
    cudaGetSymbolAddress((void**)&p_qkv, g_qkv);
    cudaGetSymbolAddress((void**)&p_attn, g_attn);
    cudaGetSymbolAddress((void**)&p_x2, g_x2);
    cudaGetSymbolAddress((void**)&p_g, g_g);
    cudaGetSymbolAddress((void**)&p_wqkv, g_wqkv);
    cudaGetSymbolAddress((void**)&p_wproj, g_wproj);
    cudaGetSymbolAddress((void**)&p_wfc1, g_wfc1);
    cudaGetSymbolAddress((void**)&p_wfc2, g_wfc2);

    static bool attr_done = false;
    if (!attr_done) {
        cudaFuncSetAttribute(hmma_gemm<0, __half>, cudaFuncAttributeMaxDynamicSharedMemorySize, GEMM_DYN);
        cudaFuncSetAttribute(hmma_gemm<1, __half>, cudaFuncAttributeMaxDynamicSharedMemorySize, GEMM_DYN);
        cudaFuncSetAttribute(hmma_gemm<2, float>,  cudaFuncAttributeMaxDynamicSharedMemorySize, GEMM_DYN);
        attr_done = true;
    }

    // 0. weight conversion
    {
        int n;
        n = 3 * DIMC * DIMC / 4; f2h_kernel<<<(n + 255) / 256, 256>>>(qkv_w, p_wqkv, n);
        n = DIMC * DIMC / 4;     f2h_kernel<<<(n + 255) / 256, 256>>>(proj_w, p_wproj, n);
        n = MLPH * DIMC / 4;     f2h_kernel<<<(n + 255) / 256, 256>>>(fc1_w, p_wfc1, n);
        n = DIMC * MLPH / 4;     f2h_kernel<<<(n + 255) / 256, 256>>>(fc2_w, p_wfc2, n);
    }

    // 1. LN1
    ln_kernel<<<MROWS, 256>>>(x, ln1_w, ln1_b, p_ln);

    // 2. QKV
    {
        dim3 grid(3 * DIMC / BN, MROWS / BM);
        hmma_gemm<0, __half><<<grid, 256, GEMM_DYN>>>(p_ln, p_wqkv, qkv_b, nullptr, p_qkv,
                                                      MROWS, 3 * DIMC, DIMC);
    }

    // 3. Windowed attention
    {
        dim3 grid(SEQ / WIN, HEADS, BATCH);
        attn_kernel<<<grid, 128>>>(p_qkv, p_attn);
    }

    // 4. Proj + residual
    {
        dim3 grid(DIMC / BN, MROWS / BM);
        hmma_gemm<2, float><<<grid, 256, GEMM_DYN>>>(p_attn, p_wproj, proj_b, x, p_x2,
                                                     MROWS, DIMC, DIMC);
    }

    // 5. LN2
    ln_kernel<<<MROWS, 256>>>(p_x2, ln2_w, ln2_b, p_ln);

    // 6. FC1 + GELU
    {
        dim3 grid(MLPH / BN, MROWS / BM);
        hmma_gemm<1, __half><<<grid, 256, GEMM_DYN>>>(p_ln, p_wfc1, fc1_b, nullptr, p_g,
                                                      MROWS, MLPH, DIMC);
    }

    // 7. FC2 + residual
    {
        dim3 grid(DIMC / BN, MROWS / BM);
        hmma_gemm<2, float><<<grid, 256, GEMM_DYN>>>(p_g, p_wfc2, fc2_b, p_x2, out,
                                                     MROWS, DIMC, MLPH);
    }
}

// round 11
// speedup vs baseline: 1.1976x; 1.0617x over previous
#include <cuda_runtime.h>
#include <cuda_fp16.h>
#include <math.h>
#include <stdint.h>

#define DIMC 1024
#define HEADS 16
#define HDIM 64
#define WIN 128
#define SEQ 8192
#define BATCH 4
#define MROWS (BATCH * SEQ)        // 32768
#define MLPH 2048
#define EPSLN 1e-5f

// ---------------- scratch (device globals; no runtime allocation) ----------
__device__ __half g_ln[(size_t)MROWS * DIMC];
__device__ __half g_qkv[(size_t)MROWS * 3 * DIMC];
__device__ __half g_attn[(size_t)MROWS * DIMC];
__device__ float  g_x2[(size_t)MROWS * DIMC];
__device__ __half g_g[(size_t)MROWS * MLPH];
__device__ __half g_wqkv[(size_t)3 * DIMC * DIMC];
__device__ __half g_wproj[(size_t)DIMC * DIMC];
__device__ __half g_wfc1[(size_t)MLPH * DIMC];
__device__ __half g_wfc2[(size_t)DIMC * MLPH];

// ---------------- helpers ---------------------------------------------------
__device__ __forceinline__ uint32_t s2u(const void* p) {
    uint32_t r;
    asm("{ .reg .u64 t; cvta.to.shared.u64 t, %1; cvt.u32.u64 %0, t; }" : "=r"(r) : "l"(p));
    return r;
}

typedef unsigned long long u64t;

__device__ __forceinline__ u64t pk2(float x, float y) {
    u64t r; asm("mov.b64 %0, {%1, %2};" : "=l"(r) : "f"(x), "f"(y)); return r;
}
__device__ __forceinline__ u64t bc2(float x) {
    u64t r; asm("mov.b64 %0, {%1, %1};" : "=l"(r) : "f"(x)); return r;
}
__device__ __forceinline__ float2 upk2(u64t v) {
    float2 f; asm("mov.b64 {%0, %1}, %2;" : "=f"(f.x), "=f"(f.y) : "l"(v)); return f;
}
__device__ __forceinline__ u64t fma2(u64t a, u64t b, u64t c) {
    u64t d; asm("fma.rn.f32x2 %0, %1, %2, %3;" : "=l"(d) : "l"(a), "l"(b), "l"(c)); return d;
}
__device__ __forceinline__ u64t mul2(u64t a, u64t b) {
    u64t d; asm("mul.rn.f32x2 %0, %1, %2;" : "=l"(d) : "l"(a), "l"(b)); return d;
}

// ---------------- fp32 -> fp16 converter -----------------------------------
__global__ void f2h_kernel(const float* __restrict__ src, __half* __restrict__ dst, int n4) {
    int i = blockIdx.x * blockDim.x + threadIdx.x;
    if (i < n4) {
        float4 v = reinterpret_cast<const float4*>(src)[i];
        reinterpret_cast<__half2*>(dst)[2 * i]     = __floats2half2_rn(v.x, v.y);
        reinterpret_cast<__half2*>(dst)[2 * i + 1] = __floats2half2_rn(v.z, v.w);
    }
}

// ---------------- LayerNorm (fp32 in, half out) ----------------------------
__global__ void ln_kernel(const float* __restrict__ x, const float* __restrict__ w,
                          const float* __restrict__ b, __half* __restrict__ out) {
    __shared__ float s_sum[8], s_sq[8];
    int row = blockIdx.x;
    const float4* xr = reinterpret_cast<const float4*>(x + (size_t)row * DIMC);
    float4 v = xr[threadIdx.x];
    float s = v.x + v.y + v.z + v.w;
    float q = v.x * v.x + v.y * v.y + v.z * v.z + v.w * v.w;
#pragma unroll
    for (int o = 16; o; o >>= 1) {
        s += __shfl_xor_sync(0xffffffffu, s, o);
        q += __shfl_xor_sync(0xffffffffu, q, o);
    }
    int warp = threadIdx.x >> 5, lane = threadIdx.x & 31;
    if (lane == 0) { s_sum[warp] = s; s_sq[warp] = q; }
    __syncthreads();
    float ts = 0.f, tq = 0.f;
#pragma unroll
    for (int i = 0; i < 8; i++) { ts += s_sum[i]; tq += s_sq[i]; }
    float mean = ts * (1.f / DIMC);
    float var = tq * (1.f / DIMC) - mean * mean;
    float rstd = rsqrtf(var + EPSLN);
    float4 wv = reinterpret_cast<const float4*>(w)[threadIdx.x];
    float4 bv = reinterpret_cast<const float4*>(b)[threadIdx.x];
    __half2 h0 = __floats2half2_rn((v.x - mean) * rstd * wv.x + bv.x,
                                   (v.y - mean) * rstd * wv.y + bv.y);
    __half2 h1 = __floats2half2_rn((v.z - mean) * rstd * wv.z + bv.z,
                                   (v.w - mean) * rstd * wv.w + bv.w);
    reinterpret_cast<__half2*>(out + (size_t)row * DIMC)[2 * threadIdx.x] = h0;
    reinterpret_cast<__half2*>(out + (size_t)row * DIMC)[2 * threadIdx.x + 1] = h1;
}

// ---------------- fp16 HMMA GEMM, 128x128 block, 64x32 warp tile -----------
// (unchanged from round-9 winner)
#define BM 128
#define BN 128
#define BK 32
#define STAGES 4
#define ROWB 80                         // row stride bytes (32 halves + 8 pad)
#define A_STG_B (BM * ROWB)             // 10240
#define B_STG_B (BN * ROWB)             // 10240
#define GEMM_DYN (STAGES * (A_STG_B + B_STG_B) + 256)  // ~82.2 KB

template <int EPI, typename OT>
__global__ __launch_bounds__(256, 2)
void hmma_gemm(const __half* __restrict__ A, const __half* __restrict__ W,
               const float* __restrict__ bias, const float* __restrict__ res,
               OT* __restrict__ C, int M, int N, int K) {
    extern __shared__ char dsm[];
    const uint32_t sbase = (s2u(dsm) + 127u) & ~127u;
    const uint32_t aoff = sbase;
    const uint32_t boff = sbase + STAGES * A_STG_B;

    const int tid = threadIdx.x;
    const int lane = tid & 31, warp = tid >> 5;
    const int warp_m = warp >> 2, warp_n = warp & 3;
    const int grp = lane >> 2, tig = lane & 3;
    const int m0 = blockIdx.y * BM, n0 = blockIdx.x * BN;

    const __half* Ab = A + (size_t)m0 * K;
    const __half* Wb = W + (size_t)n0 * K;

    const int aRowL = (lane & 7) + ((lane >> 3) & 1) * 8;
    const int aKL   = (lane >> 4) * 8;
    const int bRowL = (lane & 7) + ((lane >> 4) & 1) * 8;
    const int bKL   = ((lane >> 3) & 1) * 8;

    float acc[4][4][4];
#pragma unroll
    for (int mt = 0; mt < 4; mt++)
#pragma unroll
        for (int nt = 0; nt < 4; nt++)
#pragma unroll
            for (int i = 0; i < 4; i++) acc[mt][nt][i] = 0.f;

    auto load_stage = [&](int chunk, int s) {
        const int kc = chunk * BK;
        const uint32_t abuf = aoff + s * A_STG_B;
        const uint32_t bbuf = boff + s * B_STG_B;
#pragma unroll
        for (int i = 0; i < 2; i++) {
            int flat = tid + i * 256;
            int row = flat >> 2, cg = flat & 3;
            const void* srca = Ab + (size_t)row * K + kc + cg * 8;
            uint32_t dsta = abuf + row * ROWB + cg * 16;
            asm volatile("cp.async.cg.shared.global [%0], [%1], 16;" :: "r"(dsta), "l"(srca));
            const void* srcb = Wb + (size_t)row * K + kc + cg * 8;
            uint32_t dstb = bbuf + row * ROWB + cg * 16;
            asm volatile("cp.async.cg.shared.global [%0], [%1], 16;" :: "r"(dstb), "l"(srcb));
        }
        asm volatile("cp.async.commit_group;");
    };

    const int KIT = K / BK;
#pragma unroll
    for (int p = 0; p < STAGES - 1; p++) load_stage(p, p);

    for (int it = 0; it < KIT; ++it) {
        asm volatile("cp.async.wait_group %0;" :: "n"(STAGES - 2));
        __syncthreads();

        const int nxt = it + STAGES - 1;
        if (nxt < KIT) load_stage(nxt, nxt % STAGES);

        const int s = it % STAGES;
        const uint32_t abufs = aoff + s * A_STG_B;
        const uint32_t bbufs = boff + s * B_STG_B;

#pragma unroll
        for (int kb = 0; kb < BK; kb += 16) {
            unsigned af[4][4], bf[2][4];
#pragma unroll
            for (int mt = 0; mt < 4; mt++) {
                uint32_t addr = abufs + (uint32_t)(warp_m * 64 + mt * 16 + aRowL) * ROWB +
                                (uint32_t)(kb + aKL) * 2;
                asm volatile("ldmatrix.sync.aligned.m8n8.x4.shared.b16 {%0,%1,%2,%3}, [%4];"
                             : "=r"(af[mt][0]), "=r"(af[mt][1]), "=r"(af[mt][2]), "=r"(af[mt][3])
                             : "r"(addr));
            }
#pragma unroll
            for (int ntp = 0; ntp < 2; ntp++) {
                uint32_t addr = bbufs + (uint32_t)(warp_n * 32 + ntp * 16 + bRowL) * ROWB +
                                (uint32_t)(kb + bKL) * 2;
                asm volatile("ldmatrix.sync.aligned.m8n8.x4.shared.b16 {%0,%1,%2,%3}, [%4];"
                             : "=r"(bf[ntp][0]), "=r"(bf[ntp][1]), "=r"(bf[ntp][2]), "=r"(bf[ntp][3])
                             : "r"(addr));
            }
#pragma unroll
            for (int mt = 0; mt < 4; mt++)
#pragma unroll
                for (int nt = 0; nt < 4; nt++) {
                    const unsigned* bb = &bf[nt >> 1][(nt & 1) * 2];
                    asm volatile(
                        "mma.sync.aligned.m16n8k16.row.col.f32.f16.f16.f32 "
                        "{%0,%1,%2,%3}, {%4,%5,%6,%7}, {%8,%9}, {%0,%1,%2,%3};"
                        : "+f"(acc[mt][nt][0]), "+f"(acc[mt][nt][1]),
                          "+f"(acc[mt][nt][2]), "+f"(acc[mt][nt][3])
                        : "r"(af[mt][0]), "r"(af[mt][1]), "r"(af[mt][2]), "r"(af[mt][3]),
                          "r"(bb[0]), "r"(bb[1]));
                }
        }
    }

#pragma unroll
    for (int mt = 0; mt < 4; mt++) {
#pragma unroll
        for (int half_ = 0; half_ < 2; half_++) {
            int r = m0 + warp_m * 64 + mt * 16 + grp + half_ * 8;
#pragma unroll
            for (int nt = 0; nt < 4; nt++) {
                int c = n0 + warp_n * 32 + nt * 8 + tig * 2;
                float v0 = acc[mt][nt][half_ * 2 + 0] + __ldg(&bias[c]);
                float v1 = acc[mt][nt][half_ * 2 + 1] + __ldg(&bias[c + 1]);
                if (EPI == 1) {
                    v0 = 0.5f * v0 * (1.0f + erff(v0 * 0.70710678118654752f));
                    v1 = 0.5f * v1 * (1.0f + erff(v1 * 0.70710678118654752f));
                }
                if (EPI == 2) {
                    const float2 rr = *reinterpret_cast<const float2*>(res + (size_t)r * N + c);
                    v0 += rr.x; v1 += rr.y;
                }
                if (sizeof(OT) == 2) {
                    *reinterpret_cast<__half2*>((__half*)C + (size_t)r * N + c) =
                        __floats2half2_rn(v0, v1);
                } else {
                    *reinterpret_cast<float2*>((float*)C + (size_t)r * N + c) =
                        make_float2(v0, v1);
                }
            }
        }
    }
}

// ---------------- Windowed attention (f32x2 packed math) --------------------
__global__ __launch_bounds__(128)
void attn_kernel(const __half* __restrict__ qkv, __half* __restrict__ out) {
    __shared__ __align__(16) float ks[64 * 64];
    __shared__ __align__(16) float vs[64 * 64];
    int w = blockIdx.x, h = blockIdx.y, b = blockIdx.z;
    int q = threadIdx.x;
    size_t rowbase = ((size_t)b * SEQ + (size_t)w * WIN);

    const __half2* qrow = reinterpret_cast<const __half2*>(
        qkv + (rowbase + q) * (3 * DIMC) + h * HDIM);
    u64t qv2[32];
#pragma unroll
    for (int i = 0; i < 32; i++) {
        float2 a = __half22float2(qrow[i]);
        qv2[i] = pk2(a.x, a.y);
    }

    float m = -1e30f, l = 0.f;
    u64t acc2[32];
    const u64t zero2 = pk2(0.f, 0.f);
#pragma unroll
    for (int i = 0; i < 32; i++) acc2[i] = zero2;

    for (int c = 0; c < 2; c++) {
        __syncthreads();
        {
            int r = threadIdx.x >> 1;
            int part = threadIdx.x & 1;
            const __half2* krow = reinterpret_cast<const __half2*>(
                qkv + (rowbase + c * 64 + r) * (3 * DIMC) + DIMC + h * HDIM + part * 32);
            const __half2* vrow = reinterpret_cast<const __half2*>(
                qkv + (rowbase + c * 64 + r) * (3 * DIMC) + 2 * DIMC + h * HDIM + part * 32);
            float* kd = &ks[r * 64 + part * 32];
            float* vd = &vs[r * 64 + part * 32];
#pragma unroll
            for (int i = 0; i < 16; i++) {
                float2 kf = __half22float2(krow[i]);
                float2 vf = __half22float2(vrow[i]);
                kd[2 * i] = kf.x; kd[2 * i + 1] = kf.y;
                vd[2 * i] = vf.x; vd[2 * i + 1] = vf.y;
            }
        }
        __syncthreads();

        for (int j = 0; j < 64; j++) {
            const u64t* kj = reinterpret_cast<const u64t*>(&ks[j * 64]);
            u64t s2 = zero2;
#pragma unroll
            for (int i = 0; i < 32; i++) s2 = fma2(qv2[i], kj[i], s2);
            float2 sf = upk2(s2);
            float s = (sf.x + sf.y) * 0.125f;

            float mn = fmaxf(m, s);
            float corr = __expf(m - mn);
            float p = __expf(s - mn);
            l = l * corr + p;
            m = mn;

            const u64t corrp = bc2(corr);
            const u64t pp = bc2(p);
            const u64t* vj = reinterpret_cast<const u64t*>(&vs[j * 64]);
#pragma unroll
            for (int i = 0; i < 32; i++)
                acc2[i] = fma2(acc2[i], corrp, mul2(pp, vj[i]));
        }
    }

    float inv = 1.f / l;
    __half2* orow = reinterpret_cast<__half2*>(out + (rowbase + q) * DIMC + h * HDIM);
#pragma unroll
    for (int i = 0; i < 32; i++) {
        float2 o = upk2(acc2[i]);
        orow[i] = __floats2half2_rn(o.x * inv, o.y * inv);
    }
}

// ---------------- launch --------------------------------------------------
extern "C" void kernel_launch(void* const* d_in, const int* in_sizes, int n_in,
                              void* d_out, int out_size) {
    const float* x      = (const float*)d_in[0];
    const float* ln1_w  = (const float*)d_in[1];
    const float* ln1_b  = (const float*)d_in[2];
    const float* qkv_w  = (const float*)d_in[3];
    const float* qkv_b  = (const float*)d_in[4];
    const float* proj_w = (const float*)d_in[5];
    const float* proj_b = (const float*)d_in[6];
    const float* ln2_w  = (const float*)d_in[7];
    const float* ln2_b  = (const float*)d_in[8];
    const float* fc1_w  = (const float*)d_in[9];
    const float* fc1_b  = (const float*)d_in[10];
    const float* fc2_w  = (const float*)d_in[11];
    const float* fc2_b  = (const float*)d_in[12];
    float* out = (float*)d_out;

    __half *p_ln, *p_qkv, *p_attn, *p_g, *p_wqkv, *p_wproj, *p_wfc1, *p_wfc2;
    float* p_x2;
    cudaGetSymbolAddress((void**)&p_ln, g_ln);
    cudaGetSymbolAddress((void**)&p_qkv, g_qkv);
    cudaGetSymbolAddress((void**)&p_attn, g_attn);
    cudaGetSymbolAddress((void**)&p_x2, g_x2);
    cudaGetSymbolAddress((void**)&p_g, g_g);
    cudaGetSymbolAddress((void**)&p_wqkv, g_wqkv);
    cudaGetSymbolAddress((void**)&p_wproj, g_wproj);
    cudaGetSymbolAddress((void**)&p_wfc1, g_wfc1);
    cudaGetSymbolAddress((void**)&p_wfc2, g_wfc2);

    static bool attr_done = false;
    if (!attr_done) {
        cudaFuncSetAttribute(hmma_gemm<0, __half>, cudaFuncAttributeMaxDynamicSharedMemorySize, GEMM_DYN);
        cudaFuncSetAttribute(hmma_gemm<1, __half>, cudaFuncAttributeMaxDynamicSharedMemorySize, GEMM_DYN);
        cudaFuncSetAttribute(hmma_gemm<2, float>,  cudaFuncAttributeMaxDynamicSharedMemorySize, GEMM_DYN);
        attr_done = true;
    }

    // 0. weight conversion
    {
        int n;
        n = 3 * DIMC * DIMC / 4; f2h_kernel<<<(n + 255) / 256, 256>>>(qkv_w, p_wqkv, n);
        n = DIMC * DIMC / 4;     f2h_kernel<<<(n + 255) / 256, 256>>>(proj_w, p_wproj, n);
        n = MLPH * DIMC / 4;     f2h_kernel<<<(n + 255) / 256, 256>>>(fc1_w, p_wfc1, n);
        n = DIMC * MLPH / 4;     f2h_kernel<<<(n + 255) / 256, 256>>>(fc2_w, p_wfc2, n);
    }

    // 1. LN1
    ln_kernel<<<MROWS, 256>>>(x, ln1_w, ln1_b, p_ln);

    // 2. QKV
    {
        dim3 grid(3 * DIMC / BN, MROWS / BM);
        hmma_gemm<0, __half><<<grid, 256, GEMM_DYN>>>(p_ln, p_wqkv, qkv_b, nullptr, p_qkv,
                                                      MROWS, 3 * DIMC, DIMC);
    }

    // 3. Windowed attention
    {
        dim3 grid(SEQ / WIN, HEADS, BATCH);
        attn_kernel<<<grid, 128>>>(p_qkv, p_attn);
    }

    // 4. Proj + residual
    {
        dim3 grid(DIMC / BN, MROWS / BM);
        hmma_gemm<2, float><<<grid, 256, GEMM_DYN>>>(p_attn, p_wproj, proj_b, x, p_x2,
                                                     MROWS, DIMC, DIMC);
    }

    // 5. LN2
    ln_kernel<<<MROWS, 256>>>(p_x2, ln2_w, ln2_b, p_ln);

    // 6. FC1 + GELU
    {
        dim3 grid(MLPH / BN, MROWS / BM);
        hmma_gemm<1, __half><<<grid, 256, GEMM_DYN>>>(p_ln, p_wfc1, fc1_b, nullptr, p_g,
                                                      MROWS, MLPH, DIMC);
    }

    // 7. FC2 + residual
    {
        dim3 grid(DIMC / BN, MROWS / BM);
        hmma_gemm<2, float><<<grid, 256, GEMM_DYN>>>(p_g, p_wfc2, fc2_b, p_x2, out,
                                                     MROWS, DIMC, MLPH);
    }
}

// round 17
// speedup vs baseline: 1.5717x; 1.3124x over previous
#include <cuda_runtime.h>
#include <cuda_fp16.h>
#include <math.h>
#include <stdint.h>

#define DIMC 1024
#define HEADS 16
#define HDIM 64
#define WIN 128
#define SEQ 8192
#define BATCH 4
#define MROWS (BATCH * SEQ)        // 32768
#define MLPH 2048
#define EPSLN 1e-5f

// ---------------- scratch (device globals; no runtime allocation) ----------
__device__ __half g_ln[(size_t)MROWS * DIMC];
__device__ __half g_qkv[(size_t)MROWS * 3 * DIMC];
__device__ __half g_attn[(size_t)MROWS * DIMC];
__device__ float  g_x2[(size_t)MROWS * DIMC];
__device__ __half g_g[(size_t)MROWS * MLPH];
__device__ __half g_wqkv[(size_t)3 * DIMC * DIMC];
__device__ __half g_wproj[(size_t)DIMC * DIMC];
__device__ __half g_wfc1[(size_t)MLPH * DIMC];
__device__ __half g_wfc2[(size_t)DIMC * MLPH];

// ---------------- helpers ---------------------------------------------------
__device__ __forceinline__ uint32_t s2u(const void* p) {
    uint32_t r;
    asm("{ .reg .u64 t; cvta.to.shared.u64 t, %1; cvt.u32.u64 %0, t; }" : "=r"(r) : "l"(p));
    return r;
}

__device__ __forceinline__ void sts32(uint32_t addr, uint32_t val) {
    asm volatile("st.shared.b32 [%0], %1;" :: "r"(addr), "r"(val) : "memory");
}

// ---------------- fp32 -> fp16 converter -----------------------------------
__global__ void f2h_kernel(const float* __restrict__ src, __half* __restrict__ dst, int n4) {
    int i = blockIdx.x * blockDim.x + threadIdx.x;
    if (i < n4) {
        float4 v = reinterpret_cast<const float4*>(src)[i];
        reinterpret_cast<__half2*>(dst)[2 * i]     = __floats2half2_rn(v.x, v.y);
        reinterpret_cast<__half2*>(dst)[2 * i + 1] = __floats2half2_rn(v.z, v.w);
    }
}

// ---------------- LayerNorm (fp32 in, half out) ----------------------------
__global__ void ln_kernel(const float* __restrict__ x, const float* __restrict__ w,
                          const float* __restrict__ b, __half* __restrict__ out) {
    __shared__ float s_sum[8], s_sq[8];
    int row = blockIdx.x;
    const float4* xr = reinterpret_cast<const float4*>(x + (size_t)row * DIMC);
    float4 v = xr[threadIdx.x];
    float s = v.x + v.y + v.z + v.w;
    float q = v.x * v.x + v.y * v.y + v.z * v.z + v.w * v.w;
#pragma unroll
    for (int o = 16; o; o >>= 1) {
        s += __shfl_xor_sync(0xffffffffu, s, o);
        q += __shfl_xor_sync(0xffffffffu, q, o);
    }
    int warp = threadIdx.x >> 5, lane = threadIdx.x & 31;
    if (lane == 0) { s_sum[warp] = s; s_sq[warp] = q; }
    __syncthreads();
    float ts = 0.f, tq = 0.f;
#pragma unroll
    for (int i = 0; i < 8; i++) { ts += s_sum[i]; tq += s_sq[i]; }
    float mean = ts * (1.f / DIMC);
    float var = tq * (1.f / DIMC) - mean * mean;
    float rstd = rsqrtf(var + EPSLN);
    float4 wv = reinterpret_cast<const float4*>(w)[threadIdx.x];
    float4 bv = reinterpret_cast<const float4*>(b)[threadIdx.x];
    __half2 h0 = __floats2half2_rn((v.x - mean) * rstd * wv.x + bv.x,
                                   (v.y - mean) * rstd * wv.y + bv.y);
    __half2 h1 = __floats2half2_rn((v.z - mean) * rstd * wv.z + bv.z,
                                   (v.w - mean) * rstd * wv.w + bv.w);
    reinterpret_cast<__half2*>(out + (size_t)row * DIMC)[2 * threadIdx.x] = h0;
    reinterpret_cast<__half2*>(out + (size_t)row * DIMC)[2 * threadIdx.x + 1] = h1;
}

// ---------------- fp16 HMMA GEMM, 128x128 block, 64x32 warp tile -----------
// (unchanged from round-9 winner)
#define BM 128
#define BN 128
#define BK 32
#define STAGES 4
#define ROWB 80                         // row stride bytes (32 halves + 8 pad)
#define A_STG_B (BM * ROWB)             // 10240
#define B_STG_B (BN * ROWB)             // 10240
#define GEMM_DYN (STAGES * (A_STG_B + B_STG_B) + 256)  // ~82.2 KB

template <int EPI, typename OT>
__global__ __launch_bounds__(256, 2)
void hmma_gemm(const __half* __restrict__ A, const __half* __restrict__ W,
               const float* __restrict__ bias, const float* __restrict__ res,
               OT* __restrict__ C, int M, int N, int K) {
    extern __shared__ char dsm[];
    const uint32_t sbase = (s2u(dsm) + 127u) & ~127u;
    const uint32_t aoff = sbase;
    const uint32_t boff = sbase + STAGES * A_STG_B;

    const int tid = threadIdx.x;
    const int lane = tid & 31, warp = tid >> 5;
    const int warp_m = warp >> 2, warp_n = warp & 3;
    const int grp = lane >> 2, tig = lane & 3;
    const int m0 = blockIdx.y * BM, n0 = blockIdx.x * BN;

    const __half* Ab = A + (size_t)m0 * K;
    const __half* Wb = W + (size_t)n0 * K;

    const int aRowL = (lane & 7) + ((lane >> 3) & 1) * 8;
    const int aKL   = (lane >> 4) * 8;
    const int bRowL = (lane & 7) + ((lane >> 4) & 1) * 8;
    const int bKL   = ((lane >> 3) & 1) * 8;

    float acc[4][4][4];
#pragma unroll
    for (int mt = 0; mt < 4; mt++)
#pragma unroll
        for (int nt = 0; nt < 4; nt++)
#pragma unroll
            for (int i = 0; i < 4; i++) acc[mt][nt][i] = 0.f;

    auto load_stage = [&](int chunk, int s) {
        const int kc = chunk * BK;
        const uint32_t abuf = aoff + s * A_STG_B;
        const uint32_t bbuf = boff + s * B_STG_B;
#pragma unroll
        for (int i = 0; i < 2; i++) {
            int flat = tid + i * 256;
            int row = flat >> 2, cg = flat & 3;
            const void* srca = Ab + (size_t)row * K + kc + cg * 8;
            uint32_t dsta = abuf + row * ROWB + cg * 16;
            asm volatile("cp.async.cg.shared.global [%0], [%1], 16;" :: "r"(dsta), "l"(srca));
            const void* srcb = Wb + (size_t)row * K + kc + cg * 8;
            uint32_t dstb = bbuf + row * ROWB + cg * 16;
            asm volatile("cp.async.cg.shared.global [%0], [%1], 16;" :: "r"(dstb), "l"(srcb));
        }
        asm volatile("cp.async.commit_group;");
    };

    const int KIT = K / BK;
#pragma unroll
    for (int p = 0; p < STAGES - 1; p++) load_stage(p, p);

    for (int it = 0; it < KIT; ++it) {
        asm volatile("cp.async.wait_group %0;" :: "n"(STAGES - 2));
        __syncthreads();

        const int nxt = it + STAGES - 1;
        if (nxt < KIT) load_stage(nxt, nxt % STAGES);

        const int s = it % STAGES;
        const uint32_t abufs = aoff + s * A_STG_B;
        const uint32_t bbufs = boff + s * B_STG_B;

#pragma unroll
        for (int kb = 0; kb < BK; kb += 16) {
            unsigned af[4][4], bf[2][4];
#pragma unroll
            for (int mt = 0; mt < 4; mt++) {
                uint32_t addr = abufs + (uint32_t)(warp_m * 64 + mt * 16 + aRowL) * ROWB +
                                (uint32_t)(kb + aKL) * 2;
                asm volatile("ldmatrix.sync.aligned.m8n8.x4.shared.b16 {%0,%1,%2,%3}, [%4];"
                             : "=r"(af[mt][0]), "=r"(af[mt][1]), "=r"(af[mt][2]), "=r"(af[mt][3])
                             : "r"(addr));
            }
#pragma unroll
            for (int ntp = 0; ntp < 2; ntp++) {
                uint32_t addr = bbufs + (uint32_t)(warp_n * 32 + ntp * 16 + bRowL) * ROWB +
                                (uint32_t)(kb + bKL) * 2;
                asm volatile("ldmatrix.sync.aligned.m8n8.x4.shared.b16 {%0,%1,%2,%3}, [%4];"
                             : "=r"(bf[ntp][0]), "=r"(bf[ntp][1]), "=r"(bf[ntp][2]), "=r"(bf[ntp][3])
                             : "r"(addr));
            }
#pragma unroll
            for (int mt = 0; mt < 4; mt++)
#pragma unroll
                for (int nt = 0; nt < 4; nt++) {
                    const unsigned* bb = &bf[nt >> 1][(nt & 1) * 2];
                    asm volatile(
                        "mma.sync.aligned.m16n8k16.row.col.f32.f16.f16.f32 "
                        "{%0,%1,%2,%3}, {%4,%5,%6,%7}, {%8,%9}, {%0,%1,%2,%3};"
                        : "+f"(acc[mt][nt][0]), "+f"(acc[mt][nt][1]),
                          "+f"(acc[mt][nt][2]), "+f"(acc[mt][nt][3])
                        : "r"(af[mt][0]), "r"(af[mt][1]), "r"(af[mt][2]), "r"(af[mt][3]),
                          "r"(bb[0]), "r"(bb[1]));
                }
        }
    }

#pragma unroll
    for (int mt = 0; mt < 4; mt++) {
#pragma unroll
        for (int half_ = 0; half_ < 2; half_++) {
            int r = m0 + warp_m * 64 + mt * 16 + grp + half_ * 8;
#pragma unroll
            for (int nt = 0; nt < 4; nt++) {
                int c = n0 + warp_n * 32 + nt * 8 + tig * 2;
                float v0 = acc[mt][nt][half_ * 2 + 0] + __ldg(&bias[c]);
                float v1 = acc[mt][nt][half_ * 2 + 1] + __ldg(&bias[c + 1]);
                if (EPI == 1) {
                    v0 = 0.5f * v0 * (1.0f + erff(v0 * 0.70710678118654752f));
                    v1 = 0.5f * v1 * (1.0f + erff(v1 * 0.70710678118654752f));
                }
                if (EPI == 2) {
                    const float2 rr = *reinterpret_cast<const float2*>(res + (size_t)r * N + c);
                    v0 += rr.x; v1 += rr.y;
                }
                if (sizeof(OT) == 2) {
                    *reinterpret_cast<__half2*>((__half*)C + (size_t)r * N + c) =
                        __floats2half2_rn(v0, v1);
                } else {
                    *reinterpret_cast<float2*>((float*)C + (size_t)r * N + c) =
                        make_float2(v0, v1);
                }
            }
        }
    }
}

// ---------------- Windowed attention on HMMA --------------------------------
// One block per (window, head, batch). 256 threads, 8 warps (2 M x 4 N).
// S = Q K^T (128x128, k=64) -> softmax (full window) -> O = P V (k=128).
// Q/K/V smem rows: 144 B (64 halves + 8 pad). P rows: 272 B (128 halves + 8 pad).
// P overlays Q+K after S phase. V read via ldmatrix.trans as B operand.

#define AT_QKV_STRIDE 144
#define AT_P_STRIDE 272
#define ATT_DYN (3 * 128 * AT_QKV_STRIDE)   // 55296 B

__global__ __launch_bounds__(256)
void attn_mma_kernel(const __half* __restrict__ qkv, __half* __restrict__ out) {
    extern __shared__ char dsm[];
    __shared__ float smax[128 * 4];
    __shared__ float ssum[128 * 4];

    const uint32_t sbase = s2u(dsm);
    const uint32_t sQ = sbase;
    const uint32_t sK = sbase + 128 * AT_QKV_STRIDE;
    const uint32_t sV = sbase + 2 * 128 * AT_QKV_STRIDE;
    const uint32_t sP = sbase;  // overlays Q+K (34816 <= 36864)

    const int w = blockIdx.x, h = blockIdx.y, b = blockIdx.z;
    const int tid = threadIdx.x, lane = tid & 31, warp = tid >> 5;
    const int wm = warp >> 2, wn = warp & 3;
    const int grp = lane >> 2, tig = lane & 3;
    const size_t rowbase = ((size_t)b * SEQ + (size_t)w * WIN);

    // ---- load Q,K,V (each 128 rows x 128B) via cp.async ----
    const __half* base = qkv + rowbase * (3 * DIMC) + h * HDIM;
#pragma unroll
    for (int i = 0; i < 4; i++) {
        int c = tid + i * 256;           // 0..1023
        int row = c >> 3, cg = c & 7;
        const __half* src = base + (size_t)row * (3 * DIMC) + cg * 8;
        uint32_t d = (uint32_t)(row * AT_QKV_STRIDE + cg * 16);
        asm volatile("cp.async.cg.shared.global [%0], [%1], 16;" :: "r"(sQ + d), "l"(src));
        asm volatile("cp.async.cg.shared.global [%0], [%1], 16;" :: "r"(sK + d), "l"(src + DIMC));
        asm volatile("cp.async.cg.shared.global [%0], [%1], 16;" :: "r"(sV + d), "l"(src + 2 * DIMC));
    }
    asm volatile("cp.async.commit_group;");
    asm volatile("cp.async.wait_group 0;");
    __syncthreads();

    const int aRowL = (lane & 7) + ((lane >> 3) & 1) * 8;
    const int aKL   = (lane >> 4) * 8;
    const int bRowL = (lane & 7) + ((lane >> 4) & 1) * 8;
    const int bKL   = ((lane >> 3) & 1) * 8;

    // ---- S = Q K^T : warp tile 64x32, k=64 ----
    float sacc[4][4][4];
#pragma unroll
    for (int mt = 0; mt < 4; mt++)
#pragma unroll
        for (int nt = 0; nt < 4; nt++)
#pragma unroll
            for (int i = 0; i < 4; i++) sacc[mt][nt][i] = 0.f;

#pragma unroll
    for (int kb = 0; kb < 64; kb += 16) {
        unsigned af[4][4], bf[2][4];
#pragma unroll
        for (int mt = 0; mt < 4; mt++) {
            uint32_t addr = sQ + (uint32_t)(wm * 64 + mt * 16 + aRowL) * AT_QKV_STRIDE +
                            (uint32_t)(kb + aKL) * 2;
            asm volatile("ldmatrix.sync.aligned.m8n8.x4.shared.b16 {%0,%1,%2,%3}, [%4];"
                         : "=r"(af[mt][0]), "=r"(af[mt][1]), "=r"(af[mt][2]), "=r"(af[mt][3])
                         : "r"(addr));
        }
#pragma unroll
        for (int ntp = 0; ntp < 2; ntp++) {
            uint32_t addr = sK + (uint32_t)(wn * 32 + ntp * 16 + bRowL) * AT_QKV_STRIDE +
                            (uint32_t)(kb + bKL) * 2;
            asm volatile("ldmatrix.sync.aligned.m8n8.x4.shared.b16 {%0,%1,%2,%3}, [%4];"
                         : "=r"(bf[ntp][0]), "=r"(bf[ntp][1]), "=r"(bf[ntp][2]), "=r"(bf[ntp][3])
                         : "r"(addr));
        }
#pragma unroll
        for (int mt = 0; mt < 4; mt++)
#pragma unroll
            for (int nt = 0; nt < 4; nt++) {
                const unsigned* bb = &bf[nt >> 1][(nt & 1) * 2];
                asm volatile(
                    "mma.sync.aligned.m16n8k16.row.col.f32.f16.f16.f32 "
                    "{%0,%1,%2,%3}, {%4,%5,%6,%7}, {%8,%9}, {%0,%1,%2,%3};"
                    : "+f"(sacc[mt][nt][0]), "+f"(sacc[mt][nt][1]),
                      "+f"(sacc[mt][nt][2]), "+f"(sacc[mt][nt][3])
                    : "r"(af[mt][0]), "r"(af[mt][1]), "r"(af[mt][2]), "r"(af[mt][3]),
                      "r"(bb[0]), "r"(bb[1]));
            }
    }

    // ---- softmax: row max ----
    float pm[4][2];
#pragma unroll
    for (int mt = 0; mt < 4; mt++)
#pragma unroll
        for (int hf = 0; hf < 2; hf++) {
            float mmx = -1e30f;
#pragma unroll
            for (int nt = 0; nt < 4; nt++) {
                mmx = fmaxf(mmx, sacc[mt][nt][hf * 2]);
                mmx = fmaxf(mmx, sacc[mt][nt][hf * 2 + 1]);
            }
            mmx *= 0.125f;
            mmx = fmaxf(mmx, __shfl_xor_sync(0xffffffffu, mmx, 1));
            mmx = fmaxf(mmx, __shfl_xor_sync(0xffffffffu, mmx, 2));
            pm[mt][hf] = mmx;
        }
    if (tig == 0) {
#pragma unroll
        for (int mt = 0; mt < 4; mt++)
#pragma unroll
            for (int hf = 0; hf < 2; hf++) {
                int row = wm * 64 + mt * 16 + grp + hf * 8;
                smax[row * 4 + wn] = pm[mt][hf];
            }
    }
    __syncthreads();   // smax visible; S phase (Q/K reads) complete

    // ---- exp + row sums + write P (overlays Q/K) via st.shared ----
#pragma unroll
    for (int mt = 0; mt < 4; mt++) {
#pragma unroll
        for (int hf = 0; hf < 2; hf++) {
            int row = wm * 64 + mt * 16 + grp + hf * 8;
            float rm = fmaxf(fmaxf(smax[row * 4 + 0], smax[row * 4 + 1]),
                             fmaxf(smax[row * 4 + 2], smax[row * 4 + 3]));
            float psum = 0.f;
#pragma unroll
            for (int nt = 0; nt < 4; nt++) {
                float p0 = __expf(fmaf(sacc[mt][nt][hf * 2],     0.125f, -rm));
                float p1 = __expf(fmaf(sacc[mt][nt][hf * 2 + 1], 0.125f, -rm));
                psum += p0 + p1;
                int col = wn * 32 + nt * 8 + tig * 2;
                __half2 ph = __floats2half2_rn(p0, p1);
                uint32_t pbits = *reinterpret_cast<uint32_t*>(&ph);
                sts32(sP + (uint32_t)row * AT_P_STRIDE + (uint32_t)col * 2, pbits);
            }
            psum += __shfl_xor_sync(0xffffffffu, psum, 1);
            psum += __shfl_xor_sync(0xffffffffu, psum, 2);
            if (tig == 0) ssum[row * 4 + wn] = psum;
        }
    }
    __syncthreads();

    // ---- O = P V : warp tile 64x16, k=128, V via ldmatrix.trans ----
    const int vRowL = (lane & 7) + ((lane >> 3) & 1) * 8;
    const int vDL   = (lane >> 4) * 8;

    float oacc[4][2][4];
#pragma unroll
    for (int mt = 0; mt < 4; mt++)
#pragma unroll
        for (int nt = 0; nt < 2; nt++)
#pragma unroll
            for (int i = 0; i < 4; i++) oacc[mt][nt][i] = 0.f;

#pragma unroll
    for (int kt = 0; kt < 8; kt++) {
        unsigned paf[4][4], vbf[4];
#pragma unroll
        for (int mt = 0; mt < 4; mt++) {
            uint32_t addr = sP + (uint32_t)(wm * 64 + mt * 16 + aRowL) * AT_P_STRIDE +
                            (uint32_t)(kt * 16 + aKL) * 2;
            asm volatile("ldmatrix.sync.aligned.m8n8.x4.shared.b16 {%0,%1,%2,%3}, [%4];"
                         : "=r"(paf[mt][0]), "=r"(paf[mt][1]), "=r"(paf[mt][2]), "=r"(paf[mt][3])
                         : "r"(addr));
        }
        {
            uint32_t addr = sV + (uint32_t)(kt * 16 + vRowL) * AT_QKV_STRIDE +
                            (uint32_t)(wn * 16 + vDL) * 2;
            asm volatile("ldmatrix.sync.aligned.m8n8.x4.trans.shared.b16 {%0,%1,%2,%3}, [%4];"
                         : "=r"(vbf[0]), "=r"(vbf[1]), "=r"(vbf[2]), "=r"(vbf[3])
                         : "r"(addr));
        }
#pragma unroll
        for (int mt = 0; mt < 4; mt++)
#pragma unroll
            for (int nt = 0; nt < 2; nt++) {
                asm volatile(
                    "mma.sync.aligned.m16n8k16.row.col.f32.f16.f16.f32 "
                    "{%0,%1,%2,%3}, {%4,%5,%6,%7}, {%8,%9}, {%0,%1,%2,%3};"
                    : "+f"(oacc[mt][nt][0]), "+f"(oacc[mt][nt][1]),
                      "+f"(oacc[mt][nt][2]), "+f"(oacc[mt][nt][3])
                    : "r"(paf[mt][0]), "r"(paf[mt][1]), "r"(paf[mt][2]), "r"(paf[mt][3]),
                      "r"(vbf[nt * 2]), "r"(vbf[nt * 2 + 1]));
            }
    }

    // ---- normalize + store ----
#pragma unroll
    for (int mt = 0; mt < 4; mt++) {
#pragma unroll
        for (int hf = 0; hf < 2; hf++) {
            int row = wm * 64 + mt * 16 + grp + hf * 8;
            float l = ssum[row * 4 + 0] + ssum[row * 4 + 1] +
                      ssum[row * 4 + 2] + ssum[row * 4 + 3];
            float inv = 1.f / l;
#pragma unroll
            for (int nt = 0; nt < 2; nt++) {
                int col = wn * 16 + nt * 8 + tig * 2;
                __half2 hv = __floats2half2_rn(oacc[mt][nt][hf * 2] * inv,
                                               oacc[mt][nt][hf * 2 + 1] * inv);
                *reinterpret_cast<__half2*>(out + (rowbase + row) * DIMC + h * HDIM + col) = hv;
            }
        }
    }
}

// ---------------- launch --------------------------------------------------
extern "C" void kernel_launch(void* const* d_in, const int* in_sizes, int n_in,
                              void* d_out, int out_size) {
    const float* x      = (const float*)d_in[0];
    const float* ln1_w  = (const float*)d_in[1];
    const float* ln1_b  = (const float*)d_in[2];
    const float* qkv_w  = (const float*)d_in[3];
    const float* qkv_b  = (const float*)d_in[4];
    const float* proj_w = (const float*)d_in[5];
    const float* proj_b = (const float*)d_in[6];
    const float* ln2_w  = (const float*)d_in[7];
    const float* ln2_b  = (const float*)d_in[8];
    const float* fc1_w  = (const float*)d_in[9];
    const float* fc1_b  = (const float*)d_in[10];
    const float* fc2_w  = (const float*)d_in[11];
    const float* fc2_b  = (const float*)d_in[12];
    float* out = (float*)d_out;

    __half *p_ln, *p_qkv, *p_attn, *p_g, *p_wqkv, *p_wproj, *p_wfc1, *p_wfc2;
    float* p_x2;
    cudaGetSymbolAddress((void**)&p_ln, g_ln);
    cudaGetSymbolAddress((void**)&p_qkv, g_qkv);
    cudaGetSymbolAddress((void**)&p_attn, g_attn);
    cudaGetSymbolAddress((void**)&p_x2, g_x2);
    cudaGetSymbolAddress((void**)&p_g, g_g);
    cudaGetSymbolAddress((void**)&p_wqkv, g_wqkv);
    cudaGetSymbolAddress((void**)&p_wproj, g_wproj);
    cudaGetSymbolAddress((void**)&p_wfc1, g_wfc1);
    cudaGetSymbolAddress((void**)&p_wfc2, g_wfc2);

    static bool attr_done = false;
    if (!attr_done) {
        cudaFuncSetAttribute(hmma_gemm<0, __half>, cudaFuncAttributeMaxDynamicSharedMemorySize, GEMM_DYN);
        cudaFuncSetAttribute(hmma_gemm<1, __half>, cudaFuncAttributeMaxDynamicSharedMemorySize, GEMM_DYN);
        cudaFuncSetAttribute(hmma_gemm<2, float>,  cudaFuncAttributeMaxDynamicSharedMemorySize, GEMM_DYN);
        cudaFuncSetAttribute(attn_mma_kernel, cudaFuncAttributeMaxDynamicSharedMemorySize, ATT_DYN);
        attr_done = true;
    }

    // 0. weight conversion
    {
        int n;
        n = 3 * DIMC * DIMC / 4; f2h_kernel<<<(n + 255) / 256, 256>>>(qkv_w, p_wqkv, n);
        n = DIMC * DIMC / 4;     f2h_kernel<<<(n + 255) / 256, 256>>>(proj_w, p_wproj, n);
        n = MLPH * DIMC / 4;     f2h_kernel<<<(n + 255) / 256, 256>>>(fc1_w, p_wfc1, n);
        n = DIMC * MLPH / 4;     f2h_kernel<<<(n + 255) / 256, 256>>>(fc2_w, p_wfc2, n);
    }

    // 1. LN1
    ln_kernel<<<MROWS, 256>>>(x, ln1_w, ln1_b, p_ln);

    // 2. QKV
    {
        dim3 grid(3 * DIMC / BN, MROWS / BM);
        hmma_gemm<0, __half><<<grid, 256, GEMM_DYN>>>(p_ln, p_wqkv, qkv_b, nullptr, p_qkv,
                                                      MROWS, 3 * DIMC, DIMC);
    }

    // 3. Windowed attention (HMMA)
    {
        dim3 grid(SEQ / WIN, HEADS, BATCH);
        attn_mma_kernel<<<grid, 256, ATT_DYN>>>(p_qkv, p_attn);
    }

    // 4. Proj + residual
    {
        dim3 grid(DIMC / BN, MROWS / BM);
        hmma_gemm<2, float><<<grid, 256, GEMM_DYN>>>(p_attn, p_wproj, proj_b, x, p_x2,
                                                     MROWS, DIMC, DIMC);
    }

    // 5. LN2
    ln_kernel<<<MROWS, 256>>>(p_x2, ln2_w, ln2_b, p_ln);

    // 6. FC1 + GELU
    {
        dim3 grid(MLPH / BN, MROWS / BM);
        hmma_gemm<1, __half><<<grid, 256, GEMM_DYN>>>(p_ln, p_wfc1, fc1_b, nullptr, p_g,
                                                      MROWS, MLPH, DIMC);
    }

    // 7. FC2 + residual
    {
        dim3 grid(DIMC / BN, MROWS / BM);
        hmma_gemm<2, float><<<grid, 256, GEMM_DYN>>>(p_g, p_wfc2, fc2_b, p_x2, out,
                                                     MROWS, DIMC, MLPH);
    }
}